// round 1
// baseline (speedup 1.0000x reference)
#include <cuda_runtime.h>
#include <cstdint>

// ---------------------------------------------------------------------------
// QuanvolutionClassifier closed form:
//   z_k = alpha[wire] * cos(p_k) + beta[wire] * sin(p_k)
//   logits = feats @ w.T + bias ; out = log_softmax(logits)
// Folded: logits[b,c] = bias[c] + sum_px Wa[c,px]*cos(x[b,px]) + Wb[c,px]*sin(x[b,px])
// ---------------------------------------------------------------------------

#define SW_FLOATS (784 * 20)
#define THREADS 256
#define WARPS 8
#define CHUNK 98
#define XPITCH 33
#define SX_OFF SW_FLOATS                      // floats
#define SX_FLOATS (WARPS * 32 * XPITCH)       // 8448
#define SMEM_BYTES ((SW_FLOATS + SX_FLOATS) * 4)  // 96512

__device__ __align__(16) float g_wfold[SW_FLOATS];

typedef unsigned long long u64;

__device__ __forceinline__ u64 pack2(float x, float y) {
    u64 r; asm("mov.b64 %0, {%1, %2};" : "=l"(r) : "f"(x), "f"(y)); return r;
}
__device__ __forceinline__ u64 fma2(u64 a, u64 b, u64 c) {
    u64 d; asm("fma.rn.f32x2 %0, %1, %2, %3;" : "=l"(d) : "l"(a), "l"(b), "l"(c)); return d;
}
__device__ __forceinline__ float2 unpack2(u64 v) {
    float2 f; asm("mov.b64 {%0, %1}, %2;" : "=f"(f.x), "=f"(f.y) : "l"(v)); return f;
}

struct c2f { float x, y; };
__device__ __forceinline__ c2f cmulf(c2f a, c2f b) {
    return { a.x * b.x - a.y * b.y, a.x * b.y + a.y * b.x };
}

// ---------------------------------------------------------------------------
// Prep: compose per-wire SU(2), derive (alpha, beta), fold into weights
// indexed by raw pixel order.
// ---------------------------------------------------------------------------
__global__ void quanv_prep_kernel(const float* __restrict__ params,
                                  const float* __restrict__ wmat, int depth) {
    __shared__ float sa[4], sb[4];
    int tid = threadIdx.x;
    if (tid < 4) {
        int wire = tid;
        // U columns: (a0,b0) = U e0, (a1,b1) = U e1
        c2f a0{1.f, 0.f}, b0{0.f, 0.f};
        c2f a1{0.f, 0.f}, b1{0.f, 0.f};
        b1.x = 1.f;
        for (int d = 0; d < depth; ++d) {
            float rz1 = params[(d * 4 + wire) * 3 + 0];
            float ry  = params[(d * 4 + wire) * 3 + 1];
            float rz2 = params[(d * 4 + wire) * 3 + 2];
            float c1 = cosf(0.5f * rz1), s1 = sinf(0.5f * rz1);
            c2f p1{c1, -s1}, p1c{c1, s1};
            a0 = cmulf(a0, p1);  a1 = cmulf(a1, p1);
            b0 = cmulf(b0, p1c); b1 = cmulf(b1, p1c);
            float cy = cosf(0.5f * ry), sy = sinf(0.5f * ry);
            c2f na0{cy * a0.x - sy * b0.x, cy * a0.y - sy * b0.y};
            c2f nb0{sy * a0.x + cy * b0.x, sy * a0.y + cy * b0.y};
            c2f na1{cy * a1.x - sy * b1.x, cy * a1.y - sy * b1.y};
            c2f nb1{sy * a1.x + cy * b1.x, sy * a1.y + cy * b1.y};
            a0 = na0; b0 = nb0; a1 = na1; b1 = nb1;
            float cz = cosf(0.5f * rz2), sz = sinf(0.5f * rz2);
            c2f p2{cz, -sz}, p2c{cz, sz};
            a0 = cmulf(a0, p2);  a1 = cmulf(a1, p2);
            b0 = cmulf(b0, p2c); b1 = cmulf(b1, p2c);
        }
        sa[wire] = 2.f * (a0.x * a0.x + a0.y * a0.y) - 1.f;
        sb[wire] = 2.f * (a0.x * a1.x + a0.y * a1.y);
    }
    __syncthreads();
    for (int px = tid; px < 784; px += blockDim.x) {
        int r = px / 28, cc = px - r * 28;
        int i = r >> 1, di = r & 1, j = cc >> 1, dj = cc & 1;
        int wi = di * 2 + dj;
        int k = (i * 14 + j) * 4 + wi;
        float al = sa[wi], be = sb[wi];
#pragma unroll
        for (int c = 0; c < 10; ++c) {
            float wv = wmat[c * 784 + k];
            g_wfold[px * 20 + c]      = wv * al;
            g_wfold[px * 20 + 10 + c] = wv * be;
        }
    }
}

// ---------------------------------------------------------------------------
// Main kernel: block = 32 samples (lanes) x 8 warp pixel-chunks of 98.
// Weights staged in smem, broadcast LDS.128. x staged via coalesced LDG into
// padded smem tiles (conflict-free on both store and load sides).
// ---------------------------------------------------------------------------
template <int CNT>
__device__ __forceinline__ void process_tile(const float* __restrict__ sW,
                                             const float* __restrict__ myX,
                                             int pxBase, u64 acc[5]) {
#pragma unroll
    for (int t = 0; t < CNT; ++t) {
        float p = myX[t];
        float sv, cv;
        __sincosf(p, &sv, &cv);
        u64 ccp = pack2(cv, cv);
        u64 ssp = pack2(sv, sv);
        const ulonglong2* wp =
            reinterpret_cast<const ulonglong2*>(sW + (pxBase + t) * 20);
        ulonglong2 w0 = wp[0], w1 = wp[1], w2 = wp[2], w3 = wp[3], w4 = wp[4];
        acc[0] = fma2(w0.x, ccp, acc[0]);
        acc[1] = fma2(w0.y, ccp, acc[1]);
        acc[2] = fma2(w1.x, ccp, acc[2]);
        acc[3] = fma2(w1.y, ccp, acc[3]);
        acc[4] = fma2(w2.x, ccp, acc[4]);
        acc[0] = fma2(w2.y, ssp, acc[0]);
        acc[1] = fma2(w3.x, ssp, acc[1]);
        acc[2] = fma2(w3.y, ssp, acc[2]);
        acc[3] = fma2(w4.x, ssp, acc[3]);
        acc[4] = fma2(w4.y, ssp, acc[4]);
    }
}

__global__ void __launch_bounds__(THREADS, 2)
quanv_main_kernel(const float* __restrict__ x,
                  const float* __restrict__ bias,
                  float* __restrict__ out, int B) {
    extern __shared__ float smem[];
    int tid = threadIdx.x;
    int warp = tid >> 5, lane = tid & 31;
    float* sW = smem;
    float* sXw = smem + SX_OFF + warp * (32 * XPITCH);
    float* sPart = smem + SX_OFF;  // union with sXw region (after main loop)

    // stage folded weights: 3920 float4s across 256 threads
    {
        float4* d4 = reinterpret_cast<float4*>(sW);
        const float4* g4 = reinterpret_cast<const float4*>(g_wfold);
        for (int i = tid; i < SW_FLOATS / 4; i += THREADS) d4[i] = g4[i];
    }
    __syncthreads();

    int b0 = blockIdx.x * 32;
    u64 acc[5] = {0ull, 0ull, 0ull, 0ull, 0ull};
    int chunkBase = warp * CHUNK;

    for (int off = 0; off < CHUNK; off += 32) {
        int cnt = CHUNK - off;
        if (cnt > 32) cnt = 32;
        __syncwarp();
#pragma unroll 4
        for (int s = 0; s < 32; ++s) {
            if (lane < cnt) {
                size_t b = (size_t)(b0 + s);
                sXw[s * XPITCH + lane] = x[b * 784 + chunkBase + off + lane];
            }
        }
        __syncwarp();
        const float* myX = sXw + lane * XPITCH;
        if (cnt == 32)
            process_tile<32>(sW, myX, chunkBase + off, acc);
        else
            process_tile<CHUNK % 32>(sW, myX, chunkBase + off, acc);
    }

    __syncthreads();  // all warps done reading sXw before partials overwrite it
    {
        float2* pp = reinterpret_cast<float2*>(sPart + (warp * 32 + lane) * 10);
#pragma unroll
        for (int j = 0; j < 5; ++j) pp[j] = unpack2(acc[j]);
    }
    __syncthreads();

    if (tid < 32) {
        int b = b0 + tid;
        float L[10];
#pragma unroll
        for (int c = 0; c < 10; ++c) L[c] = bias[c];
        for (int w2 = 0; w2 < WARPS; ++w2) {
            const float* pr = sPart + (w2 * 32 + tid) * 10;
#pragma unroll
            for (int c = 0; c < 10; ++c) L[c] += pr[c];
        }
        float m = L[0];
#pragma unroll
        for (int c = 1; c < 10; ++c) m = fmaxf(m, L[c]);
        float sum = 0.f;
#pragma unroll
        for (int c = 0; c < 10; ++c) sum += __expf(L[c] - m);
        float lse = m + __logf(sum);
        if (b < B) {
#pragma unroll
            for (int c = 0; c < 10; ++c) out[(size_t)b * 10 + c] = L[c] - lse;
        }
    }
}

extern "C" void kernel_launch(void* const* d_in, const int* in_sizes, int n_in,
                              void* d_out, int out_size) {
    const float* x      = (const float*)d_in[0];
    const float* params = (const float*)d_in[1];
    const float* wmat   = (const float*)d_in[2];
    const float* bias   = (const float*)d_in[3];
    float* out = (float*)d_out;

    int B = in_sizes[0] / 784;
    int depth = in_sizes[1] / 12;

    cudaFuncSetAttribute(quanv_main_kernel,
                         cudaFuncAttributeMaxDynamicSharedMemorySize, SMEM_BYTES);

    quanv_prep_kernel<<<1, 256>>>(params, wmat, depth);
    quanv_main_kernel<<<B / 32, THREADS, SMEM_BYTES>>>(x, bias, out, B);
}

// round 2
// speedup vs baseline: 1.0011x; 1.0011x over previous
#include <cuda_runtime.h>
#include <cstdint>

// ---------------------------------------------------------------------------
// QuanvolutionClassifier closed form:
//   z_k = alpha[wire] * cos(p_k) + beta[wire] * sin(p_k)
//   logits[b,c] = bias[c] + sum_px Wa[c,px]*cos(x[b,px]) + Wb[c,px]*sin(x[b,px])
// Round 2: pixel-split (2 CTAs per sample group), double-buffered cooperative
// x staging, partial logits -> scratch -> finalize kernel.
// ---------------------------------------------------------------------------

#define THREADS 256
#define WARPS 8
#define SPLIT 2
#define PX_CTA 392
#define TILE_PX 56
#define NTILES 7
#define WTILE 7
#define XPITCH 57
#define MAXB 8192

#define SW_FLOATS (PX_CTA * 20)          // 7840 floats = 31360 B
#define SX_FLOATS (2 * 32 * XPITCH)      // 3648 floats = 14592 B (2 buffers)
#define SMEM_BYTES ((SW_FLOATS + SX_FLOATS) * 4)  // 45952

__device__ __align__(16) float g_wfold[784 * 20];
__device__ float g_part[SPLIT][MAXB][10];

typedef unsigned long long u64;

__device__ __forceinline__ u64 pack2(float x, float y) {
    u64 r; asm("mov.b64 %0, {%1, %2};" : "=l"(r) : "f"(x), "f"(y)); return r;
}
__device__ __forceinline__ u64 fma2(u64 a, u64 b, u64 c) {
    u64 d; asm("fma.rn.f32x2 %0, %1, %2, %3;" : "=l"(d) : "l"(a), "l"(b), "l"(c)); return d;
}
__device__ __forceinline__ float2 unpack2(u64 v) {
    float2 f; asm("mov.b64 {%0, %1}, %2;" : "=f"(f.x), "=f"(f.y) : "l"(v)); return f;
}

struct c2f { float x, y; };
__device__ __forceinline__ c2f cmulf(c2f a, c2f b) {
    return { a.x * b.x - a.y * b.y, a.x * b.y + a.y * b.x };
}

// ---------------------------------------------------------------------------
// Prep: compose per-wire SU(2), derive (alpha, beta), fold into weights
// indexed by raw pixel order. Layout: g_wfold[px*20 + c] = Wa, [px*20+10+c] = Wb.
// ---------------------------------------------------------------------------
__global__ void quanv_prep_kernel(const float* __restrict__ params,
                                  const float* __restrict__ wmat, int depth) {
    __shared__ float sa[4], sb[4];
    int tid = threadIdx.x;
    if (tid < 4) {
        int wire = tid;
        c2f a0{1.f, 0.f}, b0{0.f, 0.f};
        c2f a1{0.f, 0.f}, b1{1.f, 0.f};
        for (int d = 0; d < depth; ++d) {
            float rz1 = params[(d * 4 + wire) * 3 + 0];
            float ry  = params[(d * 4 + wire) * 3 + 1];
            float rz2 = params[(d * 4 + wire) * 3 + 2];
            float c1 = cosf(0.5f * rz1), s1 = sinf(0.5f * rz1);
            c2f p1{c1, -s1}, p1c{c1, s1};
            a0 = cmulf(a0, p1);  a1 = cmulf(a1, p1);
            b0 = cmulf(b0, p1c); b1 = cmulf(b1, p1c);
            float cy = cosf(0.5f * ry), sy = sinf(0.5f * ry);
            c2f na0{cy * a0.x - sy * b0.x, cy * a0.y - sy * b0.y};
            c2f nb0{sy * a0.x + cy * b0.x, sy * a0.y + cy * b0.y};
            c2f na1{cy * a1.x - sy * b1.x, cy * a1.y - sy * b1.y};
            c2f nb1{sy * a1.x + cy * b1.x, sy * a1.y + cy * b1.y};
            a0 = na0; b0 = nb0; a1 = na1; b1 = nb1;
            float cz = cosf(0.5f * rz2), sz = sinf(0.5f * rz2);
            c2f p2{cz, -sz}, p2c{cz, sz};
            a0 = cmulf(a0, p2);  a1 = cmulf(a1, p2);
            b0 = cmulf(b0, p2c); b1 = cmulf(b1, p2c);
        }
        sa[wire] = 2.f * (a0.x * a0.x + a0.y * a0.y) - 1.f;
        sb[wire] = 2.f * (a0.x * a1.x + a0.y * a1.y);
    }
    __syncthreads();
    for (int px = tid; px < 784; px += blockDim.x) {
        int r = px / 28, cc = px - r * 28;
        int i = r >> 1, di = r & 1, j = cc >> 1, dj = cc & 1;
        int wi = di * 2 + dj;
        int k = (i * 14 + j) * 4 + wi;
        float al = sa[wi], be = sb[wi];
#pragma unroll
        for (int c = 0; c < 10; ++c) {
            float wv = wmat[c * 784 + k];
            g_wfold[px * 20 + c]      = wv * al;
            g_wfold[px * 20 + 10 + c] = wv * be;
        }
    }
}

// ---------------------------------------------------------------------------
// Main kernel: grid = ngroups*SPLIT. Each CTA: 32 samples x 392 pixels.
// Warp w handles 7 px per tile, 7 tiles. Lanes = samples. Weights broadcast
// from smem; x staged via double-buffered cooperative LDG.128.
// ---------------------------------------------------------------------------
__global__ void __launch_bounds__(THREADS, 3)
quanv_main_kernel(const float* __restrict__ x, int B) {
    extern __shared__ float smem[];
    float* sW = smem;                     // PX_CTA*20
    float* sX = smem + SW_FLOATS;         // 2 x [32][XPITCH]
    float* sP = smem + SW_FLOATS;         // partials overlay (after last sync)

    int tid = threadIdx.x;
    int warp = tid >> 5, lane = tid & 31;
    int half = blockIdx.x & 1;
    int grp  = blockIdx.x >> 1;
    int b0 = grp * 32;
    int pxBase = half * PX_CTA;

    // stage folded weights for this half: 1960 float4
    {
        float4* d4 = reinterpret_cast<float4*>(sW);
        const float4* g4 = reinterpret_cast<const float4*>(g_wfold + pxBase * 20);
        for (int i = tid; i < SW_FLOATS / 4; i += THREADS) d4[i] = g4[i];
    }

    // per-thread staging coordinates: tile is 448 float4 (32 samples x 14 f4)
    int i0 = tid;                 // first float4 index
    int s0 = i0 / 14, c0 = i0 - s0 * 14;
    int i1 = tid + 256;           // second float4 index (tid < 192)
    int s1 = i1 / 14, c1 = i1 - s1 * 14;
    int r0 = b0 + s0; if (r0 >= B) r0 = B - 1;
    int r1 = b0 + s1; if (r1 >= B) r1 = B - 1;
    const float* gx0 = x + (size_t)r0 * 784 + pxBase + c0 * 4;
    const float* gx1 = x + (size_t)r1 * 784 + pxBase + c1 * 4;
    bool has2 = (tid < 192);

    // prefetch tile 0
    float4 pa = *reinterpret_cast<const float4*>(gx0);
    float4 pb = has2 ? *reinterpret_cast<const float4*>(gx1)
                     : make_float4(0.f, 0.f, 0.f, 0.f);

    u64 acc[5] = {0ull, 0ull, 0ull, 0ull, 0ull};

#pragma unroll
    for (int t = 0; t < NTILES; ++t) {
        float* sXb = sX + (t & 1) * (32 * XPITCH);
        // store prefetched tile
        {
            float* d0 = sXb + s0 * XPITCH + c0 * 4;
            d0[0] = pa.x; d0[1] = pa.y; d0[2] = pa.z; d0[3] = pa.w;
            if (has2) {
                float* d1 = sXb + s1 * XPITCH + c1 * 4;
                d1[0] = pb.x; d1[1] = pb.y; d1[2] = pb.z; d1[3] = pb.w;
            }
        }
        __syncthreads();
        // prefetch next tile (overlaps compute below)
        if (t < NTILES - 1) {
            pa = *reinterpret_cast<const float4*>(gx0 + (t + 1) * TILE_PX);
            if (has2) pb = *reinterpret_cast<const float4*>(gx1 + (t + 1) * TILE_PX);
        }
        // compute this warp's 7 pixels for all 32 samples (lane = sample)
        const float* myX = sXb + lane * XPITCH + warp * WTILE;
        int pxl = t * TILE_PX + warp * WTILE;
#pragma unroll
        for (int i = 0; i < WTILE; ++i) {
            float p = myX[i];
            float sv, cv;
            __sincosf(p, &sv, &cv);
            u64 ccp = pack2(cv, cv);
            u64 ssp = pack2(sv, sv);
            const ulonglong2* wp =
                reinterpret_cast<const ulonglong2*>(sW + (pxl + i) * 20);
            ulonglong2 w0 = wp[0], w1 = wp[1], w2 = wp[2], w3 = wp[3], w4 = wp[4];
            acc[0] = fma2(w0.x, ccp, acc[0]);
            acc[1] = fma2(w0.y, ccp, acc[1]);
            acc[2] = fma2(w1.x, ccp, acc[2]);
            acc[3] = fma2(w1.y, ccp, acc[3]);
            acc[4] = fma2(w2.x, ccp, acc[4]);
            acc[0] = fma2(w2.y, ssp, acc[0]);
            acc[1] = fma2(w3.x, ssp, acc[1]);
            acc[2] = fma2(w3.y, ssp, acc[2]);
            acc[3] = fma2(w4.x, ssp, acc[3]);
            acc[4] = fma2(w4.y, ssp, acc[4]);
        }
        __syncthreads();
    }

    // write per-warp partials to smem (overlay on sX; protected by last sync)
    {
        float2* pp = reinterpret_cast<float2*>(sP + (warp * 32 + lane) * 10);
#pragma unroll
        for (int j = 0; j < 5; ++j) pp[j] = unpack2(acc[j]);
    }
    __syncthreads();

    // reduce 8 warps -> global partial scratch
    for (int idx = tid; idx < 320; idx += THREADS) {
        int s = idx / 10, c = idx - s * 10;
        float v = 0.f;
#pragma unroll
        for (int w = 0; w < WARPS; ++w) v += sP[(w * 32 + s) * 10 + c];
        int b = b0 + s;
        if (b < B && b < MAXB) g_part[half][b][c] = v;
    }
}

// ---------------------------------------------------------------------------
// Finalize: sum partials + bias, log_softmax, write output.
// ---------------------------------------------------------------------------
__global__ void quanv_finalize_kernel(const float* __restrict__ bias,
                                      float* __restrict__ out, int B) {
    int s = blockIdx.x * blockDim.x + threadIdx.x;
    if (s >= B) return;
    float L[10];
#pragma unroll
    for (int c = 0; c < 10; ++c)
        L[c] = bias[c] + g_part[0][s][c] + g_part[1][s][c];
    float m = L[0];
#pragma unroll
    for (int c = 1; c < 10; ++c) m = fmaxf(m, L[c]);
    float sum = 0.f;
#pragma unroll
    for (int c = 0; c < 10; ++c) sum += __expf(L[c] - m);
    float lse = m + __logf(sum);
#pragma unroll
    for (int c = 0; c < 10; ++c) out[(size_t)s * 10 + c] = L[c] - lse;
}

extern "C" void kernel_launch(void* const* d_in, const int* in_sizes, int n_in,
                              void* d_out, int out_size) {
    const float* x      = (const float*)d_in[0];
    const float* params = (const float*)d_in[1];
    const float* wmat   = (const float*)d_in[2];
    const float* bias   = (const float*)d_in[3];
    float* out = (float*)d_out;

    int B = in_sizes[0] / 784;
    int depth = in_sizes[1] / 12;

    cudaFuncSetAttribute(quanv_main_kernel,
                         cudaFuncAttributeMaxDynamicSharedMemorySize, SMEM_BYTES);

    int ngroups = (B + 31) / 32;
    quanv_prep_kernel<<<1, 256>>>(params, wmat, depth);
    quanv_main_kernel<<<ngroups * SPLIT, THREADS, SMEM_BYTES>>>(x, B);
    quanv_finalize_kernel<<<(B + 255) / 256, 256>>>(bias, out, B);
}

// round 3
// speedup vs baseline: 1.1662x; 1.1650x over previous
#include <cuda_runtime.h>
#include <cstdint>

// ---------------------------------------------------------------------------
// QuanvolutionClassifier closed form:
//   z_k = alpha[wire] * cos(p_k) + beta[wire] * sin(p_k)
//   logits[b,c] = bias[c] + sum_px Wa[c,px]*cos(x[b,px]) + Wb[c,px]*sin(x[b,px])
// Round 3: no prep kernel (in-CTA weight fold overlapped with cold loads),
// triple-buffered x staging (1 sync/tile), pixel-split + finalize.
// ---------------------------------------------------------------------------

#define THREADS 256
#define WARPS 8
#define SPLIT 2
#define PX_CTA 392
#define TILE_PX 56
#define NTILES 7
#define WTILE 7
#define XPITCH 57
#define MAXB 8192

#define SW_FLOATS (PX_CTA * 20)            // 7840 floats = 31360 B
#define SX_FLOATS (3 * 32 * XPITCH)        // 5472 floats = 21888 B (3 buffers)
#define SMEM_BYTES ((SW_FLOATS + SX_FLOATS) * 4)  // 53248

__device__ float g_part[SPLIT][MAXB][10];

typedef unsigned long long u64;

__device__ __forceinline__ u64 pack2(float x, float y) {
    u64 r; asm("mov.b64 %0, {%1, %2};" : "=l"(r) : "f"(x), "f"(y)); return r;
}
__device__ __forceinline__ u64 fma2(u64 a, u64 b, u64 c) {
    u64 d; asm("fma.rn.f32x2 %0, %1, %2, %3;" : "=l"(d) : "l"(a), "l"(b), "l"(c)); return d;
}
__device__ __forceinline__ float2 unpack2(u64 v) {
    float2 f; asm("mov.b64 {%0, %1}, %2;" : "=f"(f.x), "=f"(f.y) : "l"(v)); return f;
}

struct c2f { float x, y; };
__device__ __forceinline__ c2f cmulf(c2f a, c2f b) {
    return { a.x * b.x - a.y * b.y, a.x * b.y + a.y * b.x };
}

// ---------------------------------------------------------------------------
// Main kernel: grid = ngroups*SPLIT. Each CTA: 32 samples x 392 pixels.
// In-CTA weight fold; warp w handles 7 px per tile, 7 tiles; lanes = samples.
// ---------------------------------------------------------------------------
__global__ void __launch_bounds__(THREADS, 3)
quanv_main_kernel(const float* __restrict__ x,
                  const float* __restrict__ params,
                  const float* __restrict__ wmat,
                  int B, int depth) {
    extern __shared__ float smem[];
    float* sW = smem;                     // PX_CTA*20
    float* sX = smem + SW_FLOATS;         // 3 x [32][XPITCH]
    float* sP = smem + SW_FLOATS;         // partials overlay (after last sync)
    __shared__ float sAB[8];              // alpha[4], beta[4]
    __shared__ float sParams[128];

    int tid = threadIdx.x;
    int warp = tid >> 5, lane = tid & 31;
    int half = blockIdx.x & 1;
    int grp  = blockIdx.x >> 1;
    int b0 = grp * 32;
    int pxBase = half * PX_CTA;

    // ---- prefetch wmat gather for the fold (before any barrier) ----
    float wv[16];
#pragma unroll
    for (int j = 0; j < 16; ++j) {
        int i = tid + j * THREADS;
        if (i < PX_CTA * 10) {
            int px = i / 10, c = i - px * 10;
            int gpx = pxBase + px;
            int r = gpx / 28, cc = gpx - r * 28;
            int wi = (r & 1) * 2 + (cc & 1);
            int k = ((r >> 1) * 14 + (cc >> 1)) * 4 + wi;
            wv[j] = __ldg(&wmat[c * 784 + k]);
        }
    }

    // ---- prefetch x tile 0 (448 float4 = 32 samples x 14 f4) ----
    int s0 = tid / 14, c0 = tid - s0 * 14;
    int i1 = tid + 256;
    int s1 = i1 / 14, c1 = i1 - s1 * 14;
    int r0 = b0 + s0; if (r0 >= B) r0 = B - 1;
    int r1 = b0 + s1; if (r1 >= B) r1 = B - 1;
    const float* gx0 = x + (size_t)r0 * 784 + pxBase + c0 * 4;
    const float* gx1 = x + (size_t)r1 * 784 + pxBase + c1 * 4;
    bool has2 = (tid < 192);

    float4 pa = *reinterpret_cast<const float4*>(gx0);
    float4 pb = has2 ? *reinterpret_cast<const float4*>(gx1)
                     : make_float4(0.f, 0.f, 0.f, 0.f);

    // ---- params -> smem (overlaps with the loads above) ----
    int np = 12 * depth;
    if (tid < np && tid < 128) sParams[tid] = params[tid];
    __syncthreads();

    // ---- lanes 0..3: compose SU(2), derive (alpha, beta) ----
    if (tid < 4) {
        int wire = tid;
        c2f a0{1.f, 0.f}, b0c{0.f, 0.f};
        c2f a1{0.f, 0.f}, b1{1.f, 0.f};
        for (int d = 0; d < depth; ++d) {
            float rz1 = sParams[(d * 4 + wire) * 3 + 0];
            float ry  = sParams[(d * 4 + wire) * 3 + 1];
            float rz2 = sParams[(d * 4 + wire) * 3 + 2];
            float c1v, s1v; __sincosf(0.5f * rz1, &s1v, &c1v);
            c2f p1{c1v, -s1v}, p1c{c1v, s1v};
            a0 = cmulf(a0, p1);  a1 = cmulf(a1, p1);
            b0c = cmulf(b0c, p1c); b1 = cmulf(b1, p1c);
            float cy, sy; __sincosf(0.5f * ry, &sy, &cy);
            c2f na0{cy * a0.x - sy * b0c.x, cy * a0.y - sy * b0c.y};
            c2f nb0{sy * a0.x + cy * b0c.x, sy * a0.y + cy * b0c.y};
            c2f na1{cy * a1.x - sy * b1.x, cy * a1.y - sy * b1.y};
            c2f nb1{sy * a1.x + cy * b1.x, sy * a1.y + cy * b1.y};
            a0 = na0; b0c = nb0; a1 = na1; b1 = nb1;
            float cz, sz; __sincosf(0.5f * rz2, &sz, &cz);
            c2f p2{cz, -sz}, p2c{cz, sz};
            a0 = cmulf(a0, p2);  a1 = cmulf(a1, p2);
            b0c = cmulf(b0c, p2c); b1 = cmulf(b1, p2c);
        }
        sAB[wire]     = 2.f * (a0.x * a0.x + a0.y * a0.y) - 1.f;
        sAB[4 + wire] = 2.f * (a0.x * a1.x + a0.y * a1.y);
    }
    __syncthreads();

    // ---- fold weights into smem ----
#pragma unroll
    for (int j = 0; j < 16; ++j) {
        int i = tid + j * THREADS;
        if (i < PX_CTA * 10) {
            int px = i / 10, c = i - px * 10;
            int gpx = pxBase + px;
            int r = gpx / 28, cc = gpx - r * 28;
            int wi = (r & 1) * 2 + (cc & 1);
            sW[px * 20 + c]      = wv[j] * sAB[wi];
            sW[px * 20 + 10 + c] = wv[j] * sAB[4 + wi];
        }
    }

    // ---- store tile 0, prefetch tile 1 ----
    {
        float* d0 = sX + s0 * XPITCH + c0 * 4;
        d0[0] = pa.x; d0[1] = pa.y; d0[2] = pa.z; d0[3] = pa.w;
        if (has2) {
            float* d1 = sX + s1 * XPITCH + c1 * 4;
            d1[0] = pb.x; d1[1] = pb.y; d1[2] = pb.z; d1[3] = pb.w;
        }
    }
    pa = *reinterpret_cast<const float4*>(gx0 + TILE_PX);
    if (has2) pb = *reinterpret_cast<const float4*>(gx1 + TILE_PX);
    __syncthreads();

    u64 acc[5] = {0ull, 0ull, 0ull, 0ull, 0ull};

#pragma unroll
    for (int t = 0; t < NTILES; ++t) {
        // store tile t+1 (in regs) into buf (t+1)%3; prefetch tile t+2.
        // Safe: last readers of buf (t+1)%3 were at iter t-2, two syncs ago.
        if (t < NTILES - 1) {
            float* sXb1 = sX + ((t + 1) % 3) * (32 * XPITCH);
            float* d0 = sXb1 + s0 * XPITCH + c0 * 4;
            d0[0] = pa.x; d0[1] = pa.y; d0[2] = pa.z; d0[3] = pa.w;
            if (has2) {
                float* d1 = sXb1 + s1 * XPITCH + c1 * 4;
                d1[0] = pb.x; d1[1] = pb.y; d1[2] = pb.z; d1[3] = pb.w;
            }
            if (t < NTILES - 2) {
                pa = *reinterpret_cast<const float4*>(gx0 + (t + 2) * TILE_PX);
                if (has2) pb = *reinterpret_cast<const float4*>(gx1 + (t + 2) * TILE_PX);
            }
        }
        // compute tile t from buf t%3 (written before the sync at end of t-1)
        const float* myX = sX + (t % 3) * (32 * XPITCH) + lane * XPITCH + warp * WTILE;
        int pxl = t * TILE_PX + warp * WTILE;
#pragma unroll
        for (int i = 0; i < WTILE; ++i) {
            float p = myX[i];
            float sv, cv;
            __sincosf(p, &sv, &cv);
            u64 ccp = pack2(cv, cv);
            u64 ssp = pack2(sv, sv);
            const ulonglong2* wp =
                reinterpret_cast<const ulonglong2*>(sW + (pxl + i) * 20);
            ulonglong2 w0 = wp[0], w1 = wp[1], w2 = wp[2], w3 = wp[3], w4 = wp[4];
            acc[0] = fma2(w0.x, ccp, acc[0]);
            acc[1] = fma2(w0.y, ccp, acc[1]);
            acc[2] = fma2(w1.x, ccp, acc[2]);
            acc[3] = fma2(w1.y, ccp, acc[3]);
            acc[4] = fma2(w2.x, ccp, acc[4]);
            acc[0] = fma2(w2.y, ssp, acc[0]);
            acc[1] = fma2(w3.x, ssp, acc[1]);
            acc[2] = fma2(w3.y, ssp, acc[2]);
            acc[3] = fma2(w4.x, ssp, acc[3]);
            acc[4] = fma2(w4.y, ssp, acc[4]);
        }
        __syncthreads();
    }

    // write per-warp partials to smem (overlay on sX; protected by last sync)
    {
        float2* pp = reinterpret_cast<float2*>(sP + (warp * 32 + lane) * 10);
#pragma unroll
        for (int j = 0; j < 5; ++j) pp[j] = unpack2(acc[j]);
    }
    __syncthreads();

    // reduce 8 warps -> global partial scratch
    for (int idx = tid; idx < 320; idx += THREADS) {
        int s = idx / 10, c = idx - s * 10;
        float v = 0.f;
#pragma unroll
        for (int w = 0; w < WARPS; ++w) v += sP[(w * 32 + s) * 10 + c];
        int b = b0 + s;
        if (b < B && b < MAXB) g_part[half][b][c] = v;
    }
}

// ---------------------------------------------------------------------------
// Finalize: sum partials + bias, log_softmax, write output.
// ---------------------------------------------------------------------------
__global__ void quanv_finalize_kernel(const float* __restrict__ bias,
                                      float* __restrict__ out, int B) {
    int s = blockIdx.x * blockDim.x + threadIdx.x;
    if (s >= B) return;
    float L[10];
#pragma unroll
    for (int c = 0; c < 10; ++c)
        L[c] = bias[c] + g_part[0][s][c] + g_part[1][s][c];
    float m = L[0];
#pragma unroll
    for (int c = 1; c < 10; ++c) m = fmaxf(m, L[c]);
    float sum = 0.f;
#pragma unroll
    for (int c = 0; c < 10; ++c) sum += __expf(L[c] - m);
    float lse = m + __logf(sum);
#pragma unroll
    for (int c = 0; c < 10; ++c) out[(size_t)s * 10 + c] = L[c] - lse;
}

extern "C" void kernel_launch(void* const* d_in, const int* in_sizes, int n_in,
                              void* d_out, int out_size) {
    const float* x      = (const float*)d_in[0];
    const float* params = (const float*)d_in[1];
    const float* wmat   = (const float*)d_in[2];
    const float* bias   = (const float*)d_in[3];
    float* out = (float*)d_out;

    int B = in_sizes[0] / 784;
    int depth = in_sizes[1] / 12;

    cudaFuncSetAttribute(quanv_main_kernel,
                         cudaFuncAttributeMaxDynamicSharedMemorySize, SMEM_BYTES);

    int ngroups = (B + 31) / 32;
    quanv_main_kernel<<<ngroups * SPLIT, THREADS, SMEM_BYTES>>>(x, params, wmat, B, depth);
    quanv_finalize_kernel<<<(B + 255) / 256, 256>>>(bias, out, B);
}

// round 4
// speedup vs baseline: 1.4074x; 1.2068x over previous
#include <cuda_runtime.h>
#include <cstdint>

// ---------------------------------------------------------------------------
// QuanvolutionClassifier closed form (phase form):
//   z_px = R_w * cos(p - phi_w)   (R, phi from composed SU(2) per wire)
//   logits[b,c] = bias[c] + sum_px (w[c,px]*R) * cos(x[b,px] - phi)
// Round 4: single fused kernel. Pixel-split SPLIT=2, cross-CTA completion
// counter; last CTA of each group does bias + log_softmax in-place.
// ---------------------------------------------------------------------------

#define THREADS 256
#define WARPS 8
#define SPLIT 2
#define PX_CTA 392
#define TILE_PX 56
#define NTILES 7
#define WTILE 7
#define XPITCH 57
#define MAXB 8192
#define NGRP (MAXB / 32)

#define SW_FLOATS (PX_CTA * 12)            // 4704 floats = 18816 B
#define SX_FLOATS (3 * 32 * XPITCH)        // 5472 floats = 21888 B
#define SMEM_BYTES ((SW_FLOATS + SX_FLOATS) * 4)  // 40704

__device__ float g_part[SPLIT][MAXB][10];
__device__ unsigned int g_flag[NGRP];

typedef unsigned long long u64;

__device__ __forceinline__ u64 pack2(float x, float y) {
    u64 r; asm("mov.b64 %0, {%1, %2};" : "=l"(r) : "f"(x), "f"(y)); return r;
}
__device__ __forceinline__ u64 fma2(u64 a, u64 b, u64 c) {
    u64 d; asm("fma.rn.f32x2 %0, %1, %2, %3;" : "=l"(d) : "l"(a), "l"(b), "l"(c)); return d;
}
__device__ __forceinline__ float2 unpack2(u64 v) {
    float2 f; asm("mov.b64 {%0, %1}, %2;" : "=f"(f.x), "=f"(f.y) : "l"(v)); return f;
}

struct c2f { float x, y; };
__device__ __forceinline__ c2f cmulf(c2f a, c2f b) {
    return { a.x * b.x - a.y * b.y, a.x * b.y + a.y * b.x };
}

// ---------------------------------------------------------------------------
__global__ void __launch_bounds__(THREADS, 3)
quanv_kernel(const float* __restrict__ x,
             const float* __restrict__ params,
             const float* __restrict__ wmat,
             const float* __restrict__ bias,
             float* __restrict__ out,
             int B, int depth) {
    extern __shared__ float smem[];
    float* sW = smem;                     // PX_CTA*12: [w'0..w'9, phi, pad]
    float* sX = smem + SW_FLOATS;         // 3 x [32][XPITCH]
    float* sP = smem + SW_FLOATS;         // partials overlay (after last sync)
    __shared__ float sRP[8];              // R[4], phi[4]
    __shared__ float sParams[64];
    __shared__ unsigned int sArriv;

    int tid = threadIdx.x;
    int warp = tid >> 5, lane = tid & 31;
    int half = blockIdx.x & 1;
    int grp  = blockIdx.x >> 1;
    int b0 = grp * 32;
    int pxBase = half * PX_CTA;

    // ---- prefetch wmat gather (before any barrier) ----
    float wv[16];
#pragma unroll
    for (int j = 0; j < 16; ++j) {
        int i = tid + j * THREADS;
        if (i < PX_CTA * 10) {
            int px = i / 10, c = i - px * 10;
            int gpx = pxBase + px;
            int r = gpx / 28, cc = gpx - r * 28;
            int wi = (r & 1) * 2 + (cc & 1);
            int k = ((r >> 1) * 14 + (cc >> 1)) * 4 + wi;
            wv[j] = __ldg(&wmat[c * 784 + k]);
        }
    }

    // ---- prefetch x tile 0 (448 float4 = 32 samples x 14 f4) ----
    int s0 = tid / 14, c0 = tid - s0 * 14;
    int i1 = tid + 256;
    int s1 = i1 / 14, c1 = i1 - s1 * 14;
    int r0 = b0 + s0; if (r0 >= B) r0 = B - 1;
    int r1 = b0 + s1; if (r1 >= B) r1 = B - 1;
    const float* gx0 = x + (size_t)r0 * 784 + pxBase + c0 * 4;
    const float* gx1 = x + (size_t)r1 * 784 + pxBase + c1 * 4;
    bool has2 = (tid < 192);

    float4 pa = *reinterpret_cast<const float4*>(gx0);
    float4 pb = has2 ? *reinterpret_cast<const float4*>(gx1)
                     : make_float4(0.f, 0.f, 0.f, 0.f);

    // ---- params -> smem ----
    int np = 12 * depth;
    if (tid < np && tid < 64) sParams[tid] = params[tid];
    __syncthreads();

    // ---- lanes 0..3: compose SU(2) -> (alpha,beta) -> (R, phi) ----
    if (tid < 4) {
        int wire = tid;
        c2f a0{1.f, 0.f}, b0c{0.f, 0.f};
        c2f a1{0.f, 0.f}, b1{1.f, 0.f};
        for (int d = 0; d < depth; ++d) {
            float rz1 = sParams[(d * 4 + wire) * 3 + 0];
            float ry  = sParams[(d * 4 + wire) * 3 + 1];
            float rz2 = sParams[(d * 4 + wire) * 3 + 2];
            float c1v, s1v; __sincosf(0.5f * rz1, &s1v, &c1v);
            c2f p1{c1v, -s1v}, p1c{c1v, s1v};
            a0 = cmulf(a0, p1);  a1 = cmulf(a1, p1);
            b0c = cmulf(b0c, p1c); b1 = cmulf(b1, p1c);
            float cy, sy; __sincosf(0.5f * ry, &sy, &cy);
            c2f na0{cy * a0.x - sy * b0c.x, cy * a0.y - sy * b0c.y};
            c2f nb0{sy * a0.x + cy * b0c.x, sy * a0.y + cy * b0c.y};
            c2f na1{cy * a1.x - sy * b1.x, cy * a1.y - sy * b1.y};
            c2f nb1{sy * a1.x + cy * b1.x, sy * a1.y + cy * b1.y};
            a0 = na0; b0c = nb0; a1 = na1; b1 = nb1;
            float cz, sz; __sincosf(0.5f * rz2, &sz, &cz);
            c2f p2{cz, -sz}, p2c{cz, sz};
            a0 = cmulf(a0, p2);  a1 = cmulf(a1, p2);
            b0c = cmulf(b0c, p2c); b1 = cmulf(b1, p2c);
        }
        float al = 2.f * (a0.x * a0.x + a0.y * a0.y) - 1.f;
        float be = 2.f * (a0.x * a1.x + a0.y * a1.y);
        sRP[wire]     = sqrtf(al * al + be * be);
        sRP[4 + wire] = atan2f(be, al);
    }
    __syncthreads();

    // ---- fold weights (w*R) + phi into smem ----
#pragma unroll
    for (int j = 0; j < 16; ++j) {
        int i = tid + j * THREADS;
        if (i < PX_CTA * 10) {
            int px = i / 10, c = i - px * 10;
            int gpx = pxBase + px;
            int r = gpx / 28, cc = gpx - r * 28;
            int wi = (r & 1) * 2 + (cc & 1);
            sW[px * 12 + c] = wv[j] * sRP[wi];
        }
    }
    for (int px = tid; px < PX_CTA; px += THREADS) {
        int gpx = pxBase + px;
        int r = gpx / 28, cc = gpx - r * 28;
        int wi = (r & 1) * 2 + (cc & 1);
        sW[px * 12 + 10] = sRP[4 + wi];
        sW[px * 12 + 11] = 0.f;
    }

    // ---- store tile 0, prefetch tile 1 ----
    {
        float* d0 = sX + s0 * XPITCH + c0 * 4;
        d0[0] = pa.x; d0[1] = pa.y; d0[2] = pa.z; d0[3] = pa.w;
        if (has2) {
            float* d1 = sX + s1 * XPITCH + c1 * 4;
            d1[0] = pb.x; d1[1] = pb.y; d1[2] = pb.z; d1[3] = pb.w;
        }
    }
    pa = *reinterpret_cast<const float4*>(gx0 + TILE_PX);
    if (has2) pb = *reinterpret_cast<const float4*>(gx1 + TILE_PX);
    __syncthreads();

    u64 acc[5] = {0ull, 0ull, 0ull, 0ull, 0ull};

#pragma unroll
    for (int t = 0; t < NTILES; ++t) {
        if (t < NTILES - 1) {
            float* sXb1 = sX + ((t + 1) % 3) * (32 * XPITCH);
            float* d0 = sXb1 + s0 * XPITCH + c0 * 4;
            d0[0] = pa.x; d0[1] = pa.y; d0[2] = pa.z; d0[3] = pa.w;
            if (has2) {
                float* d1 = sXb1 + s1 * XPITCH + c1 * 4;
                d1[0] = pb.x; d1[1] = pb.y; d1[2] = pb.z; d1[3] = pb.w;
            }
            if (t < NTILES - 2) {
                pa = *reinterpret_cast<const float4*>(gx0 + (t + 2) * TILE_PX);
                if (has2) pb = *reinterpret_cast<const float4*>(gx1 + (t + 2) * TILE_PX);
            }
        }
        const float* myX = sX + (t % 3) * (32 * XPITCH) + lane * XPITCH + warp * WTILE;
        int pxl = t * TILE_PX + warp * WTILE;
#pragma unroll
        for (int i = 0; i < WTILE; ++i) {
            float p = myX[i];
            const ulonglong2* wp =
                reinterpret_cast<const ulonglong2*>(sW + (pxl + i) * 12);
            ulonglong2 q0 = wp[0];   // w0w1, w2w3
            ulonglong2 q1 = wp[1];   // w4w5, w6w7
            ulonglong2 q2 = wp[2];   // w8w9, (phi, pad)
            float2 ph = unpack2(q2.y);
            float z = __cosf(p - ph.x);
            u64 zz = pack2(z, z);
            acc[0] = fma2(q0.x, zz, acc[0]);
            acc[1] = fma2(q0.y, zz, acc[1]);
            acc[2] = fma2(q1.x, zz, acc[2]);
            acc[3] = fma2(q1.y, zz, acc[3]);
            acc[4] = fma2(q2.x, zz, acc[4]);
        }
        __syncthreads();
    }

    // ---- per-warp partials -> smem ----
    {
        float2* pp = reinterpret_cast<float2*>(sP + (warp * 32 + lane) * 10);
#pragma unroll
        for (int j = 0; j < 5; ++j) pp[j] = unpack2(acc[j]);
    }
    __syncthreads();

    // ---- reduce 8 warps -> global partial scratch ----
    for (int idx = tid; idx < 320; idx += THREADS) {
        int s = idx / 10, c = idx - s * 10;
        float v = 0.f;
#pragma unroll
        for (int w = 0; w < WARPS; ++w) v += sP[(w * 32 + s) * 10 + c];
        int b = b0 + s;
        if (b < B && b < MAXB) g_part[half][b][c] = v;
    }

    // ---- completion counter: last CTA of the group finalizes ----
    __threadfence();
    __syncthreads();
    if (tid == 0) sArriv = atomicAdd(&g_flag[grp], 1u);
    __syncthreads();
    if (sArriv == SPLIT - 1) {
        if (tid < 32) {
            int b = b0 + tid;
            if (b < B) {
                float L[10];
#pragma unroll
                for (int c = 0; c < 10; ++c)
                    L[c] = __ldg(&bias[c])
                         + __ldcg(&g_part[0][b][c])
                         + __ldcg(&g_part[1][b][c]);
                float m = L[0];
#pragma unroll
                for (int c = 1; c < 10; ++c) m = fmaxf(m, L[c]);
                float sum = 0.f;
#pragma unroll
                for (int c = 0; c < 10; ++c) sum += __expf(L[c] - m);
                float lse = m + __logf(sum);
#pragma unroll
                for (int c = 0; c < 10; ++c) out[(size_t)b * 10 + c] = L[c] - lse;
            }
        }
        if (tid == 0) g_flag[grp] = 0u;   // reset for next graph replay
    }
}

extern "C" void kernel_launch(void* const* d_in, const int* in_sizes, int n_in,
                              void* d_out, int out_size) {
    const float* x      = (const float*)d_in[0];
    const float* params = (const float*)d_in[1];
    const float* wmat   = (const float*)d_in[2];
    const float* bias   = (const float*)d_in[3];
    float* out = (float*)d_out;

    int B = in_sizes[0] / 784;
    int depth = in_sizes[1] / 12;

    cudaFuncSetAttribute(quanv_kernel,
                         cudaFuncAttributeMaxDynamicSharedMemorySize, SMEM_BYTES);

    int ngroups = (B + 31) / 32;
    quanv_kernel<<<ngroups * SPLIT, THREADS, SMEM_BYTES>>>(
        x, params, wmat, bias, out, B, depth);
}

// round 5
// speedup vs baseline: 1.5405x; 1.0946x over previous
#include <cuda_runtime.h>
#include <cstdint>

// ---------------------------------------------------------------------------
// QuanvolutionClassifier, phase form:
//   logits[b,c] = bias[c] + sum_px (w[c,px]*R_w) * cos(x[b,px] - phi_w)
// Round 5: monolithic x prefetch via cp.async (no tiling, 3 barriers total),
// 4 px per LDS.128, balanced static warp partition, fused finalize.
// ---------------------------------------------------------------------------

#define THREADS 256
#define WARPS 8
#define SPLIT 2
#define PX_CTA 392
#define NF4 98                       // float4 quads per CTA half
#define XP4 99                       // pitch in float4 (conflict-free: gcd pattern)
#define MAXB 8192
#define NGRP (MAXB / 32)

#define SW_FLOATS (PX_CTA * 12)      // 4704 floats = 18816 B
#define SX_BYTES (32 * XP4 * 16)     // 50688 B
#define SMEM_BYTES (SW_FLOATS * 4 + SX_BYTES)   // 69504

__device__ float g_part[SPLIT][MAXB][10];
__device__ unsigned int g_flag[NGRP];

typedef unsigned long long u64;

__device__ __forceinline__ u64 pack2(float x, float y) {
    u64 r; asm("mov.b64 %0, {%1, %2};" : "=l"(r) : "f"(x), "f"(y)); return r;
}
__device__ __forceinline__ u64 fma2(u64 a, u64 b, u64 c) {
    u64 d; asm("fma.rn.f32x2 %0, %1, %2, %3;" : "=l"(d) : "l"(a), "l"(b), "l"(c)); return d;
}
__device__ __forceinline__ float2 unpack2(u64 v) {
    float2 f; asm("mov.b64 {%0, %1}, %2;" : "=f"(f.x), "=f"(f.y) : "l"(v)); return f;
}
__device__ __forceinline__ void cp_async16(uint32_t saddr, const void* gaddr) {
    asm volatile("cp.async.cg.shared.global [%0], [%1], 16;" :: "r"(saddr), "l"(gaddr));
}

struct c2f { float x, y; };
__device__ __forceinline__ c2f cmulf(c2f a, c2f b) {
    return { a.x * b.x - a.y * b.y, a.x * b.y + a.y * b.x };
}

// ---------------------------------------------------------------------------
__global__ void __launch_bounds__(THREADS, 3)
quanv_kernel(const float* __restrict__ x,
             const float* __restrict__ params,
             const float* __restrict__ wmat,
             const float* __restrict__ bias,
             float* __restrict__ out,
             int B, int depth) {
    extern __shared__ float smem[];
    float* sW = smem;                                  // PX_CTA*12
    float* sXf = smem + SW_FLOATS;                     // 32 rows x XP4 float4
    float* sP  = smem + SW_FLOATS;                     // partials overlay
    __shared__ float sRP[8];
    __shared__ float sParams[64];
    __shared__ unsigned int sArriv;

    int tid = threadIdx.x;
    int warp = tid >> 5, lane = tid & 31;
    int half = blockIdx.x & 1;
    int grp  = blockIdx.x >> 1;
    int b0 = grp * 32;
    int pxBase = half * PX_CTA;

    // ---- 1. wmat gather -> regs (LDG latency overlapped below) ----
    float wv[16];
#pragma unroll
    for (int j = 0; j < 16; ++j) {
        int i = tid + j * THREADS;
        if (i < PX_CTA * 10) {
            int px = i / 10, c = i - px * 10;
            int gpx = pxBase + px;
            int r = gpx / 28, cc = gpx - r * 28;
            int wi = (r & 1) * 2 + (cc & 1);
            int k = ((r >> 1) * 14 + (cc >> 1)) * 4 + wi;
            wv[j] = __ldg(&wmat[c * 784 + k]);
        }
    }

    // ---- 2. stage all x via cp.async: 3136 float4, 13 per thread ----
    {
        uint32_t sbase = (uint32_t)__cvta_generic_to_shared(sXf);
#pragma unroll
        for (int k = 0; k < 13; ++k) {
            int i = tid + k * THREADS;
            if (i < 32 * NF4) {
                int s = i / NF4, j = i - s * NF4;
                int b = b0 + s; if (b >= B) b = B - 1;
                const float* g = x + (size_t)b * 784 + pxBase + j * 4;
                cp_async16(sbase + (uint32_t)(s * XP4 + j) * 16u, g);
            }
        }
        asm volatile("cp.async.commit_group;");
    }

    // ---- 3. params -> smem ----
    int np = 12 * depth;
    if (tid < np && tid < 64) sParams[tid] = params[tid];
    __syncthreads();

    // ---- 4. wires 0..3: SU(2) composition -> (R, phi) ----
    if (tid < 4) {
        int wire = tid;
        c2f a0{1.f, 0.f}, b0c{0.f, 0.f};
        c2f a1{0.f, 0.f}, b1{1.f, 0.f};
        for (int d = 0; d < depth; ++d) {
            float rz1 = sParams[(d * 4 + wire) * 3 + 0];
            float ry  = sParams[(d * 4 + wire) * 3 + 1];
            float rz2 = sParams[(d * 4 + wire) * 3 + 2];
            float c1v, s1v; __sincosf(0.5f * rz1, &s1v, &c1v);
            c2f p1{c1v, -s1v}, p1c{c1v, s1v};
            a0 = cmulf(a0, p1);  a1 = cmulf(a1, p1);
            b0c = cmulf(b0c, p1c); b1 = cmulf(b1, p1c);
            float cy, sy; __sincosf(0.5f * ry, &sy, &cy);
            c2f na0{cy * a0.x - sy * b0c.x, cy * a0.y - sy * b0c.y};
            c2f nb0{sy * a0.x + cy * b0c.x, sy * a0.y + cy * b0c.y};
            c2f na1{cy * a1.x - sy * b1.x, cy * a1.y - sy * b1.y};
            c2f nb1{sy * a1.x + cy * b1.x, sy * a1.y + cy * b1.y};
            a0 = na0; b0c = nb0; a1 = na1; b1 = nb1;
            float cz, sz; __sincosf(0.5f * rz2, &sz, &cz);
            c2f p2{cz, -sz}, p2c{cz, sz};
            a0 = cmulf(a0, p2);  a1 = cmulf(a1, p2);
            b0c = cmulf(b0c, p2c); b1 = cmulf(b1, p2c);
        }
        float al = 2.f * (a0.x * a0.x + a0.y * a0.y) - 1.f;
        float be = 2.f * (a0.x * a1.x + a0.y * a1.y);
        sRP[wire]     = sqrtf(al * al + be * be);
        sRP[4 + wire] = atan2f(be, al);
    }
    __syncthreads();

    // ---- 5. fold weights (w*R) + phi into smem ----
#pragma unroll
    for (int j = 0; j < 16; ++j) {
        int i = tid + j * THREADS;
        if (i < PX_CTA * 10) {
            int px = i / 10, c = i - px * 10;
            int gpx = pxBase + px;
            int r = gpx / 28, cc = gpx - r * 28;
            int wi = (r & 1) * 2 + (cc & 1);
            sW[px * 12 + c] = wv[j] * sRP[wi];
        }
    }
    for (int px = tid; px < PX_CTA; px += THREADS) {
        int gpx = pxBase + px;
        int r = gpx / 28, cc = gpx - r * 28;
        int wi = (r & 1) * 2 + (cc & 1);
        sW[px * 12 + 10] = sRP[4 + wi];
        sW[px * 12 + 11] = 0.f;
    }
    asm volatile("cp.async.wait_group 0;");
    __syncthreads();

    // ---- 6. compute: warp w owns f4-quads [jbeg, jbeg+cnt) ----
    u64 acc[5] = {0ull, 0ull, 0ull, 0ull, 0ull};
    const float4* xrow = reinterpret_cast<const float4*>(sXf) + lane * XP4;
    int jbeg = warp * 12 + (warp < 2 ? warp : 2);

#define PROC_PX(pval, pxi)                                                   \
    {                                                                        \
        const ulonglong2* wp =                                               \
            reinterpret_cast<const ulonglong2*>(sW + (pxi) * 12);            \
        ulonglong2 q0 = wp[0], q1 = wp[1], q2 = wp[2];                       \
        float2 ph = unpack2(q2.y);                                           \
        float z = __cosf((pval) - ph.x);                                     \
        u64 zz = pack2(z, z);                                                \
        acc[0] = fma2(q0.x, zz, acc[0]);                                     \
        acc[1] = fma2(q0.y, zz, acc[1]);                                     \
        acc[2] = fma2(q1.x, zz, acc[2]);                                     \
        acc[3] = fma2(q1.y, zz, acc[3]);                                     \
        acc[4] = fma2(q2.x, zz, acc[4]);                                     \
    }

#pragma unroll 4
    for (int jj = 0; jj < 12; ++jj) {
        int j = jbeg + jj;
        float4 xv = xrow[j];
        int pxl = j * 4;
        PROC_PX(xv.x, pxl + 0);
        PROC_PX(xv.y, pxl + 1);
        PROC_PX(xv.z, pxl + 2);
        PROC_PX(xv.w, pxl + 3);
    }
    if (warp < 2) {
        int j = jbeg + 12;
        float4 xv = xrow[j];
        int pxl = j * 4;
        PROC_PX(xv.x, pxl + 0);
        PROC_PX(xv.y, pxl + 1);
        PROC_PX(xv.z, pxl + 2);
        PROC_PX(xv.w, pxl + 3);
    }
#undef PROC_PX

    // ---- 7. per-warp partials -> smem (overlay, protected by sync) ----
    __syncthreads();
    {
        float2* pp = reinterpret_cast<float2*>(sP + (warp * 32 + lane) * 10);
#pragma unroll
        for (int j = 0; j < 5; ++j) pp[j] = unpack2(acc[j]);
    }
    __syncthreads();

    // ---- 8. reduce 8 warps -> global partial scratch ----
    for (int idx = tid; idx < 320; idx += THREADS) {
        int s = idx / 10, c = idx - s * 10;
        float v = 0.f;
#pragma unroll
        for (int w = 0; w < WARPS; ++w) v += sP[(w * 32 + s) * 10 + c];
        int b = b0 + s;
        if (b < B && b < MAXB) g_part[half][b][c] = v;
    }

    // ---- 9. completion counter: last CTA of group finalizes ----
    __threadfence();
    __syncthreads();
    if (tid == 0) sArriv = atomicAdd(&g_flag[grp], 1u);
    __syncthreads();
    if (sArriv == SPLIT - 1) {
        if (tid < 32) {
            int b = b0 + tid;
            if (b < B) {
                float L[10];
#pragma unroll
                for (int c = 0; c < 10; ++c)
                    L[c] = __ldg(&bias[c])
                         + __ldcg(&g_part[0][b][c])
                         + __ldcg(&g_part[1][b][c]);
                float m = L[0];
#pragma unroll
                for (int c = 1; c < 10; ++c) m = fmaxf(m, L[c]);
                float sum = 0.f;
#pragma unroll
                for (int c = 0; c < 10; ++c) sum += __expf(L[c] - m);
                float lse = m + __logf(sum);
#pragma unroll
                for (int c = 0; c < 10; ++c) out[(size_t)b * 10 + c] = L[c] - lse;
            }
        }
        if (tid == 0) g_flag[grp] = 0u;
    }
}

extern "C" void kernel_launch(void* const* d_in, const int* in_sizes, int n_in,
                              void* d_out, int out_size) {
    const float* x      = (const float*)d_in[0];
    const float* params = (const float*)d_in[1];
    const float* wmat   = (const float*)d_in[2];
    const float* bias   = (const float*)d_in[3];
    float* out = (float*)d_out;

    int B = in_sizes[0] / 784;
    int depth = in_sizes[1] / 12;

    cudaFuncSetAttribute(quanv_kernel,
                         cudaFuncAttributeMaxDynamicSharedMemorySize, SMEM_BYTES);

    int ngroups = (B + 31) / 32;
    quanv_kernel<<<ngroups * SPLIT, THREADS, SMEM_BYTES>>>(
        x, params, wmat, bias, out, B, depth);
}